// round 1
// baseline (speedup 1.0000x reference)
#include <cuda_runtime.h>
#include <math.h>

#define BB 32
#define TT 2048
#define DD 512
#define UU 512

#define BM 128
#define BN 128
#define BK 16

#define TCH 16
#define TCHUNK (TT / TCH)   // 128

// ---- scratch (no allocations allowed) ----
__device__ float g_hb[BB * UU];          // h2 + b1 + b2   (64 KB)
__device__ float g_scores[BB * TT];      // raw scores     (256 KB)
__device__ float g_m[BB];
__device__ float g_z[BB];
__device__ float g_part[BB * TCH * DD];  // partial contexts (1 MB)

// ---------------------------------------------------------------------------
// Kernel 1: g_hb[b,u] = sum_d last[b,d]*W2[d,u] + b1[u] + b2[u]
// grid = B blocks, 512 threads (one per u)
// ---------------------------------------------------------------------------
__global__ void k_h2(const float* __restrict__ last, const float* __restrict__ W2,
                     const float* __restrict__ b1, const float* __restrict__ b2) {
    int b = blockIdx.x;
    int u = threadIdx.x;
    __shared__ float sl[DD];
    sl[u] = last[b * DD + u];
    __syncthreads();
    float acc = 0.f;
#pragma unroll 8
    for (int d = 0; d < DD; ++d)
        acc += sl[d] * W2[d * UU + u];
    g_hb[b * UU + u] = acc + b1[u] + b2[u];
}

// ---------------------------------------------------------------------------
// Kernel 2: scores[b,t] = V . tanh(full[b,t,:] @ W1 + g_hb[b,:]) + bV
// Tiled SGEMM fused with tanh/V epilogue.
// Block: 256 threads, tile BM=128 rows x BN=128 cols, BK=16, 8x8 microtile.
// Grid: (T/BM, B)
// ---------------------------------------------------------------------------
__global__ __launch_bounds__(256, 2) void k_score(
    const float* __restrict__ full, const float* __restrict__ W1,
    const float* __restrict__ V, const float* __restrict__ bV) {
    __shared__ float As[BK][BM];     // transposed A tile: As[k][row]
    __shared__ float Ws[BK][BN];     // Ws[k][col]
    __shared__ float hb[BN];
    __shared__ float vs[BN];

    const int b  = blockIdx.y;
    const int t0 = blockIdx.x * BM;
    const int tid = threadIdx.x;
    const int tx = tid & 15;         // 0..15  -> col group
    const int ty = tid >> 4;         // 0..15  -> row group
    const int r0 = ty * 8;
    const int c0 = tx * 8;

    const float* Ab = full + ((size_t)(b * TT + t0)) * DD;

    float s[8];
#pragma unroll
    for (int i = 0; i < 8; ++i) s[i] = 0.f;

    for (int uc = 0; uc < UU; uc += BN) {
        float acc[8][8];
#pragma unroll
        for (int i = 0; i < 8; ++i)
#pragma unroll
            for (int j = 0; j < 8; ++j) acc[i][j] = 0.f;

        if (tid < BN) {
            hb[tid] = g_hb[b * UU + uc + tid];
            vs[tid] = V[uc + tid];
        }

        for (int k0 = 0; k0 < DD; k0 += BK) {
            // Load A tile (128 rows x 16 k) as float4, store transposed
#pragma unroll
            for (int it = 0; it < 2; ++it) {
                int idx = tid + it * 256;          // 0..511 float4s
                int r = idx >> 2;                  // row 0..127
                int q = idx & 3;                   // which float4 in k
                float4 v4 = *(const float4*)(Ab + (size_t)r * DD + k0 + q * 4);
                As[q * 4 + 0][r] = v4.x;
                As[q * 4 + 1][r] = v4.y;
                As[q * 4 + 2][r] = v4.z;
                As[q * 4 + 3][r] = v4.w;
            }
            // Load W tile (16 k x 128 cols)
#pragma unroll
            for (int it = 0; it < 2; ++it) {
                int idx = tid + it * 256;
                int r = idx >> 5;                  // k row 0..15
                int c = (idx & 31) * 4;            // col
                *(float4*)&Ws[r][c] =
                    *(const float4*)(W1 + (size_t)(k0 + r) * UU + uc + c);
            }
            __syncthreads();

#pragma unroll
            for (int k = 0; k < BK; ++k) {
                float a[8], w[8];
                *(float4*)(a)     = *(const float4*)&As[k][r0];
                *(float4*)(a + 4) = *(const float4*)&As[k][r0 + 4];
                *(float4*)(w)     = *(const float4*)&Ws[k][c0];
                *(float4*)(w + 4) = *(const float4*)&Ws[k][c0 + 4];
#pragma unroll
                for (int i = 0; i < 8; ++i)
#pragma unroll
                    for (int j = 0; j < 8; ++j)
                        acc[i][j] += a[i] * w[j];
            }
            __syncthreads();
        }

        // epilogue: tanh + dot with V
#pragma unroll
        for (int i = 0; i < 8; ++i) {
#pragma unroll
            for (int j = 0; j < 8; ++j) {
                float y = tanhf(acc[i][j] + hb[c0 + j]);
                s[i] += y * vs[c0 + j];
            }
        }
        __syncthreads();   // protect hb/vs before next chunk reload
    }

    // deterministic reduction across tx (16 lanes of a half-warp share rows)
    const float bv = bV[0];
#pragma unroll
    for (int i = 0; i < 8; ++i) {
        float v = s[i];
        v += __shfl_xor_sync(0xffffffffu, v, 1, 16);
        v += __shfl_xor_sync(0xffffffffu, v, 2, 16);
        v += __shfl_xor_sync(0xffffffffu, v, 4, 16);
        v += __shfl_xor_sync(0xffffffffu, v, 8, 16);
        if (tx == 0) g_scores[b * TT + t0 + r0 + i] = v + bv;
    }
}

// ---------------------------------------------------------------------------
// Kernel 3: per-batch softmax stats (max, sum of exp)
// ---------------------------------------------------------------------------
__global__ void k_stats() {
    int b = blockIdx.x;
    int tid = threadIdx.x;   // 256
    __shared__ float red[256];

    float m = -INFINITY;
    for (int t = tid; t < TT; t += 256) m = fmaxf(m, g_scores[b * TT + t]);
    red[tid] = m;
    __syncthreads();
    for (int sft = 128; sft > 0; sft >>= 1) {
        if (tid < sft) red[tid] = fmaxf(red[tid], red[tid + sft]);
        __syncthreads();
    }
    m = red[0];
    __syncthreads();

    float z = 0.f;
    for (int t = tid; t < TT; t += 256) z += expf(g_scores[b * TT + t] - m);
    red[tid] = z;
    __syncthreads();
    for (int sft = 128; sft > 0; sft >>= 1) {
        if (tid < sft) red[tid] += red[tid + sft];
        __syncthreads();
    }
    if (tid == 0) { g_m[b] = m; g_z[b] = red[0]; }
}

// ---------------------------------------------------------------------------
// Kernel 4: partial weighted sums.  grid = (TCH, B), 128 threads, float4 per thread.
// ---------------------------------------------------------------------------
__global__ __launch_bounds__(128) void k_context(const float* __restrict__ full) {
    int b  = blockIdx.y;
    int tc = blockIdx.x;
    int tid = threadIdx.x;   // 128, each handles 4 consecutive d
    __shared__ float ws[TCHUNK];

    float m = g_m[b];
    ws[tid] = expf(g_scores[b * TT + tc * TCHUNK + tid] - m);
    __syncthreads();

    const float4* fp =
        (const float4*)(full + ((size_t)(b * TT + tc * TCHUNK)) * DD) + tid;
    float4 acc = make_float4(0.f, 0.f, 0.f, 0.f);
#pragma unroll 8
    for (int t = 0; t < TCHUNK; ++t) {
        float4 f = fp[(size_t)t * (DD / 4)];
        float w = ws[t];
        acc.x += w * f.x;
        acc.y += w * f.y;
        acc.z += w * f.z;
        acc.w += w * f.w;
    }
    float4* pp = (float4*)(g_part + ((size_t)(b * TCH + tc)) * DD) + tid;
    *pp = acc;
}

// ---------------------------------------------------------------------------
// Kernel 5: combine partials, divide by Z
// ---------------------------------------------------------------------------
__global__ void k_combine(float* __restrict__ out) {
    int idx = blockIdx.x * 256 + threadIdx.x;
    if (idx >= BB * DD) return;
    int b = idx / DD;
    int d = idx - b * DD;
    float acc = 0.f;
#pragma unroll
    for (int tc = 0; tc < TCH; ++tc)
        acc += g_part[((size_t)(b * TCH + tc)) * DD + d];
    out[idx] = acc / g_z[b];
}

// ---------------------------------------------------------------------------
extern "C" void kernel_launch(void* const* d_in, const int* in_sizes, int n_in,
                              void* d_out, int out_size) {
    const float* full = (const float*)d_in[0];
    const float* last = (const float*)d_in[1];
    const float* W1   = (const float*)d_in[2];
    const float* b1   = (const float*)d_in[3];
    const float* W2   = (const float*)d_in[4];
    const float* b2   = (const float*)d_in[5];
    const float* V    = (const float*)d_in[6];
    const float* bV   = (const float*)d_in[7];
    float* out = (float*)d_out;

    k_h2<<<BB, DD>>>(last, W2, b1, b2);

    dim3 gScore(TT / BM, BB);
    k_score<<<gScore, 256>>>(full, W1, V, bV);

    k_stats<<<BB, 256>>>();

    dim3 gCtx(TCH, BB);
    k_context<<<gCtx, 128>>>(full);

    k_combine<<<(BB * DD + 255) / 256, 256>>>(out);
}

// round 2
// speedup vs baseline: 2.1160x; 2.1160x over previous
#include <cuda_runtime.h>
#include <cuda_bf16.h>
#include <math.h>

#define BB 32
#define TT 2048
#define DD 512
#define UU 512

#define TCH 16
#define TCHUNK (TT / TCH)   // 128

// ---- scratch (no allocations allowed) ----
__device__ float g_hb[BB * UU];                 // h2 + b1 + b2
__device__ float g_scores[BB * TT];             // raw scores
__device__ float g_m[BB];
__device__ float g_z[BB];
__device__ float g_part[BB * TCH * DD];         // partial contexts
__device__ __nv_bfloat16 g_wt_hi[UU * DD];      // W1^T hi  [u][d]
__device__ __nv_bfloat16 g_wt_lo[UU * DD];      // W1^T lo  [u][d]

// ---------------------------------------------------------------------------
static __device__ __forceinline__ unsigned pack2(__nv_bfloat16 a, __nv_bfloat16 b) {
    return (unsigned)__bfloat16_as_ushort(a) |
           ((unsigned)__bfloat16_as_ushort(b) << 16);
}

static __device__ __forceinline__ void mma16816(float* c, const unsigned* a, const unsigned* b) {
    asm volatile(
        "mma.sync.aligned.m16n8k16.row.col.f32.bf16.bf16.f32 "
        "{%0,%1,%2,%3}, {%4,%5,%6,%7}, {%8,%9}, {%0,%1,%2,%3};"
        : "+f"(c[0]), "+f"(c[1]), "+f"(c[2]), "+f"(c[3])
        : "r"(a[0]), "r"(a[1]), "r"(a[2]), "r"(a[3]), "r"(b[0]), "r"(b[1]));
}

static __device__ __forceinline__ void ldm4(unsigned* r, const void* p) {
    unsigned addr = (unsigned)__cvta_generic_to_shared(p);
    asm volatile(
        "ldmatrix.sync.aligned.m8n8.x4.shared.b16 {%0,%1,%2,%3}, [%4];"
        : "=r"(r[0]), "=r"(r[1]), "=r"(r[2]), "=r"(r[3])
        : "r"(addr));
}

static __device__ __forceinline__ float fast_tanh(float x) {
    float e = __expf(2.f * x);
    return 1.f - __fdividef(2.f, e + 1.f);
}

// ---------------------------------------------------------------------------
// Kernel 0: split + transpose W1 -> g_wt_hi/lo  ([u][d] bf16)
// ---------------------------------------------------------------------------
__global__ void k_prep(const float* __restrict__ W1) {
    int d = blockIdx.x;
    int u = threadIdx.x;
    float x = W1[d * UU + u];
    __nv_bfloat16 hi = __float2bfloat16_rn(x);
    float r = x - __bfloat162float(hi);
    __nv_bfloat16 lo = __float2bfloat16_rn(r);
    g_wt_hi[u * DD + d] = hi;
    g_wt_lo[u * DD + d] = lo;
}

// ---------------------------------------------------------------------------
// Kernel 1: g_hb[b,u] = last[b,:] @ W2[:,u] + b1[u] + b2[u]
// ---------------------------------------------------------------------------
__global__ void k_h2(const float* __restrict__ last, const float* __restrict__ W2,
                     const float* __restrict__ b1, const float* __restrict__ b2) {
    int b = blockIdx.x;
    int u = threadIdx.x;
    __shared__ float sl[DD];
    sl[u] = last[b * DD + u];
    __syncthreads();
    float acc = 0.f;
#pragma unroll 8
    for (int d = 0; d < DD; ++d)
        acc += sl[d] * W2[d * UU + u];
    g_hb[b * UU + u] = acc + b1[u] + b2[u];
}

// ---------------------------------------------------------------------------
// Kernel 2: scores via split-bf16 HMMA GEMM + fused tanh/V epilogue.
// Block: 256 thr (8 warps), tile 128(t) x 128(u) x 32(k); warp tile 64x32.
// Smem rows padded to 40 halves -> conflict-free ldmatrix.
// ---------------------------------------------------------------------------
#define PAD 40

__global__ __launch_bounds__(256, 2) void k_score(
    const float* __restrict__ full,
    const float* __restrict__ V, const float* __restrict__ bV) {

    __shared__ __nv_bfloat16 As_hi[128 * PAD];
    __shared__ __nv_bfloat16 As_lo[128 * PAD];
    __shared__ __nv_bfloat16 Bs_hi[128 * PAD];
    __shared__ __nv_bfloat16 Bs_lo[128 * PAD];
    __shared__ float hb[128];
    __shared__ float vs[128];
    __shared__ float red[4 * 128];

    const int b   = blockIdx.y;
    const int t0  = blockIdx.x * 128;
    const int tid = threadIdx.x;
    const int wid = tid >> 5;
    const int lane = tid & 31;
    const int g = lane >> 2;
    const int t = lane & 3;
    const int mw = wid >> 2;        // 0..1
    const int nw = wid & 3;         // 0..3
    const int mbase = mw * 64;
    const int nbase = nw * 32;

    // per-lane ldmatrix offsets (in halves)
    const int tile = lane >> 3;
    const int rr = lane & 7;
    const int a_lane_off = ((tile & 1) * 8 + rr) * PAD + ((tile >> 1) & 1) * 8;
    const int b_lane_off = (((tile >> 1) & 1) * 8 + rr) * PAD + (tile & 1) * 8;

    const float* Ab = full + ((size_t)(b * TT + t0)) * DD;

    float s[8];
#pragma unroll
    for (int i = 0; i < 8; ++i) s[i] = 0.f;

    for (int uc = 0; uc < UU; uc += 128) {
        __syncthreads();            // protect hb/vs from previous epilogue
        if (tid < 128) {
            hb[tid] = g_hb[b * UU + uc + tid];
            vs[tid] = V[uc + tid];
        }

        float acc[64];
#pragma unroll
        for (int i = 0; i < 64; ++i) acc[i] = 0.f;

        for (int k0 = 0; k0 < DD; k0 += 32) {
            __syncthreads();
            // ---- load & split A: 128 rows x 32 k fp32 -> bf16 hi/lo ----
#pragma unroll
            for (int it = 0; it < 4; ++it) {
                int idx = tid + it * 256;           // 0..1023 float4s
                int r = idx >> 3;
                int q = idx & 7;
                float4 v4 = *(const float4*)(Ab + (size_t)r * DD + k0 + q * 4);
                __nv_bfloat16 h0 = __float2bfloat16_rn(v4.x);
                __nv_bfloat16 h1 = __float2bfloat16_rn(v4.y);
                __nv_bfloat16 h2 = __float2bfloat16_rn(v4.z);
                __nv_bfloat16 h3 = __float2bfloat16_rn(v4.w);
                __nv_bfloat16 l0 = __float2bfloat16_rn(v4.x - __bfloat162float(h0));
                __nv_bfloat16 l1 = __float2bfloat16_rn(v4.y - __bfloat162float(h1));
                __nv_bfloat16 l2 = __float2bfloat16_rn(v4.z - __bfloat162float(h2));
                __nv_bfloat16 l3 = __float2bfloat16_rn(v4.w - __bfloat162float(h3));
                uint2 hv, lv;
                hv.x = pack2(h0, h1); hv.y = pack2(h2, h3);
                lv.x = pack2(l0, l1); lv.y = pack2(l2, l3);
                *(uint2*)&As_hi[r * PAD + q * 4] = hv;
                *(uint2*)&As_lo[r * PAD + q * 4] = lv;
            }
            // ---- load B (pre-split, pre-transposed): 128 u x 32 k bf16 ----
#pragma unroll
            for (int it = 0; it < 2; ++it) {
                int idx = tid + it * 256;           // 0..511 uint4s
                int r = idx >> 2;
                int q = idx & 3;
                size_t so = (size_t)(uc + r) * DD + k0 + q * 8;
                *(uint4*)&Bs_hi[r * PAD + q * 8] = *(const uint4*)(g_wt_hi + so);
                *(uint4*)&Bs_lo[r * PAD + q * 8] = *(const uint4*)(g_wt_lo + so);
            }
            __syncthreads();

#pragma unroll
            for (int kk = 0; kk < 32; kk += 16) {
                unsigned bh[8], bl[8];
#pragma unroll
                for (int p = 0; p < 2; ++p) {
                    ldm4(bh + 4 * p, &Bs_hi[(nbase + p * 16) * PAD + kk + b_lane_off]);
                    ldm4(bl + 4 * p, &Bs_lo[(nbase + p * 16) * PAD + kk + b_lane_off]);
                }
#pragma unroll
                for (int mt = 0; mt < 4; ++mt) {
                    unsigned ah[4], al[4];
                    ldm4(ah, &As_hi[(mbase + mt * 16) * PAD + kk + a_lane_off]);
                    ldm4(al, &As_lo[(mbase + mt * 16) * PAD + kk + a_lane_off]);
#pragma unroll
                    for (int nt = 0; nt < 4; ++nt) {
                        float* c = acc + (mt * 4 + nt) * 4;
                        mma16816(c, ah, bh + 2 * nt);   // hi*hi
                        mma16816(c, ah, bl + 2 * nt);   // hi*lo
                        mma16816(c, al, bh + 2 * nt);   // lo*hi
                    }
                }
            }
        }

        // ---- fused epilogue: tanh + dot with V ----
#pragma unroll
        for (int mt = 0; mt < 4; ++mt) {
#pragma unroll
            for (int nt = 0; nt < 4; ++nt) {
                const float* c = acc + (mt * 4 + nt) * 4;
                int n0 = nbase + nt * 8 + 2 * t;
                float y0 = fast_tanh(c[0] + hb[n0]) * vs[n0];
                float y1 = fast_tanh(c[1] + hb[n0 + 1]) * vs[n0 + 1];
                float y2 = fast_tanh(c[2] + hb[n0]) * vs[n0];
                float y3 = fast_tanh(c[3] + hb[n0 + 1]) * vs[n0 + 1];
                s[mt * 2 + 0] += y0 + y1;
                s[mt * 2 + 1] += y2 + y3;
            }
        }
    }

    // ---- reduce: over t lanes (width 4), then over 4 n-warps via smem ----
#pragma unroll
    for (int i = 0; i < 8; ++i) {
        float v = s[i];
        v += __shfl_xor_sync(0xffffffffu, v, 1, 4);
        v += __shfl_xor_sync(0xffffffffu, v, 2, 4);
        if (t == 0) {
            int mt = i >> 1, rh = i & 1;
            int row = mbase + mt * 16 + rh * 8 + g;
            red[nw * 128 + row] = v;
        }
    }
    __syncthreads();
    if (tid < 128) {
        float sum = red[tid] + red[128 + tid] + red[256 + tid] + red[384 + tid];
        g_scores[b * TT + t0 + tid] = sum + bV[0];
    }
}

// ---------------------------------------------------------------------------
// Kernel 3: per-batch softmax stats
// ---------------------------------------------------------------------------
__global__ void k_stats() {
    int b = blockIdx.x;
    int tid = threadIdx.x;   // 256
    __shared__ float red[256];

    float m = -INFINITY;
    for (int t = tid; t < TT; t += 256) m = fmaxf(m, g_scores[b * TT + t]);
    red[tid] = m;
    __syncthreads();
    for (int sft = 128; sft > 0; sft >>= 1) {
        if (tid < sft) red[tid] = fmaxf(red[tid], red[tid + sft]);
        __syncthreads();
    }
    m = red[0];
    __syncthreads();

    float z = 0.f;
    for (int t = tid; t < TT; t += 256) z += expf(g_scores[b * TT + t] - m);
    red[tid] = z;
    __syncthreads();
    for (int sft = 128; sft > 0; sft >>= 1) {
        if (tid < sft) red[tid] += red[tid + sft];
        __syncthreads();
    }
    if (tid == 0) { g_m[b] = m; g_z[b] = red[0]; }
}

// ---------------------------------------------------------------------------
// Kernel 4: partial weighted sums
// ---------------------------------------------------------------------------
__global__ __launch_bounds__(128) void k_context(const float* __restrict__ full) {
    int b  = blockIdx.y;
    int tc = blockIdx.x;
    int tid = threadIdx.x;
    __shared__ float ws[TCHUNK];

    float m = g_m[b];
    ws[tid] = expf(g_scores[b * TT + tc * TCHUNK + tid] - m);
    __syncthreads();

    const float4* fp =
        (const float4*)(full + ((size_t)(b * TT + tc * TCHUNK)) * DD) + tid;
    float4 acc = make_float4(0.f, 0.f, 0.f, 0.f);
#pragma unroll 8
    for (int t = 0; t < TCHUNK; ++t) {
        float4 f = fp[(size_t)t * (DD / 4)];
        float w = ws[t];
        acc.x += w * f.x;
        acc.y += w * f.y;
        acc.z += w * f.z;
        acc.w += w * f.w;
    }
    float4* pp = (float4*)(g_part + ((size_t)(b * TCH + tc)) * DD) + tid;
    *pp = acc;
}

// ---------------------------------------------------------------------------
// Kernel 5: combine partials, divide by Z
// ---------------------------------------------------------------------------
__global__ void k_combine(float* __restrict__ out) {
    int idx = blockIdx.x * 256 + threadIdx.x;
    if (idx >= BB * DD) return;
    int b = idx / DD;
    int d = idx - b * DD;
    float acc = 0.f;
#pragma unroll
    for (int tc = 0; tc < TCH; ++tc)
        acc += g_part[((size_t)(b * TCH + tc)) * DD + d];
    out[idx] = acc / g_z[b];
}

// ---------------------------------------------------------------------------
extern "C" void kernel_launch(void* const* d_in, const int* in_sizes, int n_in,
                              void* d_out, int out_size) {
    const float* full = (const float*)d_in[0];
    const float* last = (const float*)d_in[1];
    const float* W1   = (const float*)d_in[2];
    const float* b1   = (const float*)d_in[3];
    const float* W2   = (const float*)d_in[4];
    const float* b2   = (const float*)d_in[5];
    const float* V    = (const float*)d_in[6];
    const float* bV   = (const float*)d_in[7];
    float* out = (float*)d_out;

    k_prep<<<DD, UU>>>(W1);
    k_h2<<<BB, DD>>>(last, W2, b1, b2);

    dim3 gScore(TT / 128, BB);
    k_score<<<gScore, 256>>>(full, V, bV);

    k_stats<<<BB, 256>>>();

    dim3 gCtx(TCH, BB);
    k_context<<<gCtx, 128>>>(full);

    k_combine<<<(BB * DD + 255) / 256, 256>>>(out);
}